// round 2
// baseline (speedup 1.0000x reference)
#include <cuda_runtime.h>
#include <math.h>

#define B_   2
#define T_   2048
#define D_   1024
#define H_   16
#define HD_  64
#define MTOK (B_ * T_)   // 4096 tokens

// ---------------- scratch (device globals; no allocations allowed) ----------
__device__ float g_xn [MTOK * D_];        // rmsnorm(x)
__device__ float g_qkr[MTOK * D_];        // rope(rmsnorm(x))
__device__ float g_qkv[3 * MTOK * D_];    // q,k,v in [B,H,T,hd]
__device__ float g_ctx[MTOK * D_];        // attention context, [B,T,D]
__device__ float g_y  [MTOK * D_];        // attn_out
__device__ float g_yn [MTOK * D_];        // rmsnorm(y)
__device__ float g_h1 [MTOK * 4 * D_];    // silu(yn@w1^T+b1)

// ---------------- RMSNorm (+ optional interleaved RoPE) ---------------------
template <bool DO_ROPE>
__global__ void __launch_bounds__(256) rmsnorm_kernel(
    const float* __restrict__ x, const float* __restrict__ scale,
    float* __restrict__ xn, float* __restrict__ qkr)
{
    int token = blockIdx.x;
    int tid   = threadIdx.x;
    const float4 v = ((const float4*)(x + (size_t)token * D_))[tid];
    float ss = v.x*v.x + v.y*v.y + v.z*v.z + v.w*v.w;
    #pragma unroll
    for (int o = 16; o; o >>= 1) ss += __shfl_xor_sync(0xffffffffu, ss, o);
    __shared__ float wsum[8];
    if ((tid & 31) == 0) wsum[tid >> 5] = ss;
    __syncthreads();
    float tot = 0.f;
    #pragma unroll
    for (int w = 0; w < 8; w++) tot += wsum[w];
    float r = rsqrtf(tot * (1.0f / D_) + 1e-6f);

    float4 sc = ((const float4*)scale)[tid];
    float4 o;
    o.x = v.x * r * sc.x; o.y = v.y * r * sc.y;
    o.z = v.z * r * sc.z; o.w = v.w * r * sc.w;
    ((float4*)(xn + (size_t)token * D_))[tid] = o;

    if (DO_ROPE) {
        int t  = token & (T_ - 1);
        int d0 = tid * 4;
        int dh = d0 & (HD_ - 1);   // even offset within head
        // theta = 10000^(-dh/64); compute in double so fp32 rounding matches ref within ~1 ulp
        float th0 = (float)exp(-(double)dh       * (9.210340371976184 / 64.0));
        float th1 = (float)exp(-(double)(dh + 2) * (9.210340371976184 / 64.0));
        float s0, c0, s1, c1;
        sincosf((float)t * th0, &s0, &c0);
        sincosf((float)t * th1, &s1, &c1);
        float4 ro;
        ro.x = o.x * c0 - o.y * s0;
        ro.y = o.y * c0 + o.x * s0;
        ro.z = o.z * c1 - o.w * s1;
        ro.w = o.w * c1 + o.z * s1;
        ((float4*)(qkr + (size_t)token * D_))[tid] = ro;
    }
}

// ---------------- tiled SGEMM: C[m][n] = sum_k A[m][k] * W[n][k] + epilogue --
enum { EPI_QKV = 0, EPI_Y = 1, EPI_SILU = 2, EPI_OUT = 3 };

template <int EPI>
__global__ void __launch_bounds__(256) gemm_kernel(
    const float* __restrict__ A1, const float* __restrict__ A2,
    const float* __restrict__ W,  const float* __restrict__ bias,
    const float* __restrict__ aux, float* __restrict__ C,
    int N, int K)
{
    __shared__ float As[8][128];
    __shared__ float Bs[8][128];
    int tid = threadIdx.x;
    int bn0 = blockIdx.x * 128;
    int bm0 = blockIdx.y * 128;
    // in_proj: q,k columns come from roped input, v columns from xn
    const float* A = (EPI == EPI_QKV && bn0 >= 2 * D_) ? A2 : A1;

    int arow = tid >> 1;          // 0..127
    int acol = (tid & 1) * 4;     // 0 or 4
    const float* Ap = A + (size_t)(bm0 + arow) * K + acol;
    const float* Wp = W + (size_t)(bn0 + arow) * K + acol;

    int tx = tid & 15, ty = tid >> 4;
    float acc[8][8];
    #pragma unroll
    for (int i = 0; i < 8; i++)
        #pragma unroll
        for (int j = 0; j < 8; j++) acc[i][j] = 0.f;

    for (int k0 = 0; k0 < K; k0 += 8) {
        float4 av = *(const float4*)(Ap + k0);
        float4 wv = *(const float4*)(Wp + k0);
        __syncthreads();
        As[acol+0][arow] = av.x; As[acol+1][arow] = av.y;
        As[acol+2][arow] = av.z; As[acol+3][arow] = av.w;
        Bs[acol+0][arow] = wv.x; Bs[acol+1][arow] = wv.y;
        Bs[acol+2][arow] = wv.z; Bs[acol+3][arow] = wv.w;
        __syncthreads();
        #pragma unroll
        for (int kk = 0; kk < 8; kk++) {
            float4 a0 = *(const float4*)&As[kk][ty * 8];
            float4 a1 = *(const float4*)&As[kk][ty * 8 + 4];
            float4 b0 = *(const float4*)&Bs[kk][tx * 8];
            float4 b1 = *(const float4*)&Bs[kk][tx * 8 + 4];
            float a[8] = {a0.x,a0.y,a0.z,a0.w,a1.x,a1.y,a1.z,a1.w};
            float b[8] = {b0.x,b0.y,b0.z,b0.w,b1.x,b1.y,b1.z,b1.w};
            #pragma unroll
            for (int i = 0; i < 8; i++)
                #pragma unroll
                for (int j = 0; j < 8; j++)
                    acc[i][j] = fmaf(a[i], b[j], acc[i][j]);
        }
    }

    #pragma unroll
    for (int i = 0; i < 8; i++) {
        int m = bm0 + ty * 8 + i;
        #pragma unroll
        for (int j = 0; j < 8; j++) {
            int n = bn0 + tx * 8 + j;
            float val = acc[i][j] + bias[n];
            if (EPI == EPI_QKV) {
                int which = n >> 10;
                int h = (n >> 6) & 15;
                int d = n & 63;
                int b = m >> 11;
                int t = m & 2047;
                C[(size_t)which * (MTOK * D_) +
                  ((size_t)(b * H_ + h) * T_ + t) * HD_ + d] = val;
            } else if (EPI == EPI_Y) {
                C[(size_t)m * N + n] = val;
            } else if (EPI == EPI_SILU) {
                C[(size_t)m * N + n] = val / (1.f + expf(-val));
            } else { // EPI_OUT: out = y + ffn
                C[(size_t)m * N + n] = aux[(size_t)m * N + n] + val;
            }
        }
    }
}

// ---------------- causal flash attention, 64x64 tiles -----------------------
// grid: (T/64, B*H), 256 threads. smem: Qs[64][65], KPs[64][65] (K then P), Vs[64][65]
__global__ void __launch_bounds__(256) attn_kernel(
    const float* __restrict__ qkv, float* __restrict__ ctx)
{
    extern __shared__ float sm[];
    float* Qs  = sm;
    float* KPs = sm + 64 * 65;
    float* Vs  = sm + 2 * 64 * 65;

    int qt  = blockIdx.x;
    int bh  = blockIdx.y;
    int tid = threadIdx.x;
    int tx  = tid & 15, ty = tid >> 4;

    const float* Qb = qkv + (size_t)bh * (T_ * HD_);
    const float* Kb = qkv + (size_t)(MTOK * D_)     + (size_t)bh * (T_ * HD_);
    const float* Vb = qkv + (size_t)2 * (MTOK * D_) + (size_t)bh * (T_ * HD_);

    { // load Q tile
        int r  = tid >> 2;
        int c0 = (tid & 3) * 16;
        #pragma unroll
        for (int u = 0; u < 4; u++) {
            int c = c0 + u * 4;
            float4 v = *(const float4*)(Qb + (size_t)(qt * 64 + r) * 64 + c);
            Qs[r*65+c] = v.x; Qs[r*65+c+1] = v.y; Qs[r*65+c+2] = v.z; Qs[r*65+c+3] = v.w;
        }
    }

    float m_i[4], l_i[4], acc[4][4];
    #pragma unroll
    for (int i = 0; i < 4; i++) {
        m_i[i] = -INFINITY; l_i[i] = 0.f;
        #pragma unroll
        for (int j = 0; j < 4; j++) acc[i][j] = 0.f;
    }

    for (int kt = 0; kt <= qt; kt++) {
        __syncthreads();   // prior-iter KPs/Vs reads done; also publishes Qs on iter 0
        {                  // load K,V tiles
            int r  = tid >> 2;
            int c0 = (tid & 3) * 16;
            #pragma unroll
            for (int u = 0; u < 4; u++) {
                int c = c0 + u * 4;
                float4 kv = *(const float4*)(Kb + (size_t)(kt * 64 + r) * 64 + c);
                KPs[r*65+c] = kv.x; KPs[r*65+c+1] = kv.y; KPs[r*65+c+2] = kv.z; KPs[r*65+c+3] = kv.w;
                float4 vv = *(const float4*)(Vb + (size_t)(kt * 64 + r) * 64 + c);
                Vs[r*65+c] = vv.x; Vs[r*65+c+1] = vv.y; Vs[r*65+c+2] = vv.z; Vs[r*65+c+3] = vv.w;
            }
        }
        __syncthreads();

        // S = Q K^T  (4x4 microtile per thread)
        float s[4][4];
        #pragma unroll
        for (int i = 0; i < 4; i++)
            #pragma unroll
            for (int j = 0; j < 4; j++) s[i][j] = 0.f;
        for (int d = 0; d < 64; d++) {
            float a[4], b[4];
            #pragma unroll
            for (int i = 0; i < 4; i++) a[i] = Qs[(ty*4+i)*65 + d];
            #pragma unroll
            for (int j = 0; j < 4; j++) b[j] = KPs[(tx*4+j)*65 + d];
            #pragma unroll
            for (int i = 0; i < 4; i++)
                #pragma unroll
                for (int j = 0; j < 4; j++) s[i][j] = fmaf(a[i], b[j], s[i][j]);
        }
        __syncthreads();   // done reading K from KPs

        // scale + causal mask (only diagonal tile needs masking)
        bool diag = (kt == qt);
        #pragma unroll
        for (int i = 0; i < 4; i++) {
            int qrow = qt * 64 + ty * 4 + i;
            #pragma unroll
            for (int j = 0; j < 4; j++) {
                int kcol = kt * 64 + tx * 4 + j;
                s[i][j] *= 0.125f;               // 1/sqrt(64)
                if (diag && kcol > qrow) s[i][j] = -1e30f;
            }
        }

        // online softmax update; stage P in KPs
        #pragma unroll
        for (int i = 0; i < 4; i++) {
            float mm = fmaxf(fmaxf(s[i][0], s[i][1]), fmaxf(s[i][2], s[i][3]));
            #pragma unroll
            for (int o = 8; o; o >>= 1) mm = fmaxf(mm, __shfl_xor_sync(0xffffffffu, mm, o));
            float mn = fmaxf(m_i[i], mm);
            float alpha = expf(m_i[i] - mn);
            m_i[i] = mn;
            float rs = 0.f;
            #pragma unroll
            for (int j = 0; j < 4; j++) {
                float p = expf(s[i][j] - mn);
                KPs[(ty*4+i)*65 + tx*4 + j] = p;
                rs += p;
            }
            #pragma unroll
            for (int o = 8; o; o >>= 1) rs += __shfl_xor_sync(0xffffffffu, rs, o);
            l_i[i] = l_i[i] * alpha + rs;
            #pragma unroll
            for (int j = 0; j < 4; j++) acc[i][j] *= alpha;
        }
        __syncthreads();   // P published

        // acc += P V
        for (int jj = 0; jj < 64; jj++) {
            float a[4], b[4];
            #pragma unroll
            for (int i = 0; i < 4; i++) a[i] = KPs[(ty*4+i)*65 + jj];
            #pragma unroll
            for (int j = 0; j < 4; j++) b[j] = Vs[jj*65 + tx*4 + j];
            #pragma unroll
            for (int i = 0; i < 4; i++)
                #pragma unroll
                for (int j = 0; j < 4; j++) acc[i][j] = fmaf(a[i], b[j], acc[i][j]);
        }
    }

    // write ctx in [B,T,D] layout (so out_proj is a plain GEMM)
    int b = bh >> 4, h = bh & 15;
    #pragma unroll
    for (int i = 0; i < 4; i++) {
        int row = qt * 64 + ty * 4 + i;
        float inv = 1.f / l_i[i];
        float4 o;
        o.x = acc[i][0]*inv; o.y = acc[i][1]*inv; o.z = acc[i][2]*inv; o.w = acc[i][3]*inv;
        *(float4*)(ctx + ((size_t)(b * T_ + row) * D_) + h * HD_ + tx * 4) = o;
    }
}

// ---------------- launch ----------------------------------------------------
extern "C" void kernel_launch(void* const* d_in, const int* in_sizes, int n_in,
                              void* d_out, int out_size)
{
    const float* x     = (const float*)d_in[0];
    const float* scale = (const float*)d_in[1];
    const float* wqkv  = (const float*)d_in[2];
    const float* bqkv  = (const float*)d_in[3];
    const float* wo    = (const float*)d_in[4];
    const float* bo    = (const float*)d_in[5];
    const float* w1    = (const float*)d_in[6];
    const float* b1    = (const float*)d_in[7];
    const float* w2    = (const float*)d_in[8];
    const float* b2    = (const float*)d_in[9];
    float* out = (float*)d_out;

    float *xn, *qkr, *qkv, *ctx, *y, *yn, *h1;
    cudaGetSymbolAddress((void**)&xn,  g_xn);
    cudaGetSymbolAddress((void**)&qkr, g_qkr);
    cudaGetSymbolAddress((void**)&qkv, g_qkv);
    cudaGetSymbolAddress((void**)&ctx, g_ctx);
    cudaGetSymbolAddress((void**)&y,   g_y);
    cudaGetSymbolAddress((void**)&yn,  g_yn);
    cudaGetSymbolAddress((void**)&h1,  g_h1);

    const int ATTN_SMEM = 3 * 64 * 65 * 4;  // 49920 B > 48K default -> opt in
    cudaFuncSetAttribute(attn_kernel, cudaFuncAttributeMaxDynamicSharedMemorySize, ATTN_SMEM);

    // 1) rmsnorm + rope
    rmsnorm_kernel<true><<<MTOK, 256>>>(x, scale, xn, qkr);
    // 2) qkv projection (q,k from roped input; v from xn), scatter to [B,H,T,hd]
    gemm_kernel<EPI_QKV><<<dim3(3 * D_ / 128, MTOK / 128), 256>>>(
        qkr, xn, wqkv, bqkv, nullptr, qkv, 3 * D_, D_);
    // 3) causal attention -> ctx [B,T,D]
    attn_kernel<<<dim3(T_ / 64, B_ * H_), 256, ATTN_SMEM>>>(qkv, ctx);
    // 4) out projection -> y
    gemm_kernel<EPI_Y><<<dim3(D_ / 128, MTOK / 128), 256>>>(
        ctx, nullptr, wo, bo, nullptr, y, D_, D_);
    // 5) rmsnorm(y) -> yn
    rmsnorm_kernel<false><<<MTOK, 256>>>(y, scale, yn, nullptr);
    // 6) ffn up + silu -> h1
    gemm_kernel<EPI_SILU><<<dim3(4 * D_ / 128, MTOK / 128), 256>>>(
        yn, nullptr, w1, b1, nullptr, h1, 4 * D_, D_);
    // 7) ffn down + residual(y) -> out
    gemm_kernel<EPI_OUT><<<dim3(D_ / 128, MTOK / 128), 256>>>(
        h1, nullptr, w2, b2, y, out, D_, 4 * D_);
}

// round 3
// speedup vs baseline: 1.0060x; 1.0060x over previous
#include <cuda_runtime.h>
#include <math.h>

#define B_   2
#define T_   2048
#define D_   1024
#define H_   16
#define HD_  64
#define MTOK (B_ * T_)   // 4096 tokens

// ---------------- scratch (device globals; no allocations allowed) ----------
__device__ float g_xn [MTOK * D_];        // rmsnorm(x)
__device__ float g_qkr[MTOK * D_];        // rope(rmsnorm(x))
__device__ float g_qkv[3 * MTOK * D_];    // q,k,v in [B,H,T,hd]
__device__ float g_ctx[MTOK * D_];        // attention context, [B,T,D]
__device__ float g_y  [MTOK * D_];        // attn_out
__device__ float g_yn [MTOK * D_];        // rmsnorm(y)
__device__ float g_h1 [MTOK * 4 * D_];    // silu(yn@w1^T+b1)

// ---------------- RMSNorm (+ optional interleaved RoPE) ---------------------
template <bool DO_ROPE>
__global__ void __launch_bounds__(256) rmsnorm_kernel(
    const float* __restrict__ x, const float* __restrict__ scale,
    float* __restrict__ xn, float* __restrict__ qkr)
{
    int token = blockIdx.x;
    int tid   = threadIdx.x;
    const float4 v = ((const float4*)(x + (size_t)token * D_))[tid];
    float ss = v.x*v.x + v.y*v.y + v.z*v.z + v.w*v.w;
    #pragma unroll
    for (int o = 16; o; o >>= 1) ss += __shfl_xor_sync(0xffffffffu, ss, o);
    __shared__ float wsum[8];
    if ((tid & 31) == 0) wsum[tid >> 5] = ss;
    __syncthreads();
    float tot = 0.f;
    #pragma unroll
    for (int w = 0; w < 8; w++) tot += wsum[w];
    float r = rsqrtf(tot * (1.0f / D_) + 1e-6f);

    float4 sc = ((const float4*)scale)[tid];
    float4 o;
    o.x = v.x * r * sc.x; o.y = v.y * r * sc.y;
    o.z = v.z * r * sc.z; o.w = v.w * r * sc.w;
    ((float4*)(xn + (size_t)token * D_))[tid] = o;

    if (DO_ROPE) {
        int t  = token & (T_ - 1);
        int d0 = tid * 4;
        int dh = d0 & (HD_ - 1);   // even offset within head
        // theta = 10000^(-dh/64); compute in double so fp32 rounding matches ref within ~1 ulp
        float th0 = (float)exp(-(double)dh       * (9.210340371976184 / 64.0));
        float th1 = (float)exp(-(double)(dh + 2) * (9.210340371976184 / 64.0));
        float s0, c0, s1, c1;
        sincosf((float)t * th0, &s0, &c0);
        sincosf((float)t * th1, &s1, &c1);
        float4 ro;
        ro.x = o.x * c0 - o.y * s0;
        ro.y = o.y * c0 + o.x * s0;
        ro.z = o.z * c1 - o.w * s1;
        ro.w = o.w * c1 + o.z * s1;
        ((float4*)(qkr + (size_t)token * D_))[tid] = ro;
    }
}

// ---------------- tiled SGEMM: C[m][n] = sum_k A[m][k] * W[n][k] + epilogue --
enum { EPI_QKV = 0, EPI_Y = 1, EPI_SILU = 2, EPI_OUT = 3 };

template <int EPI>
__global__ void __launch_bounds__(256) gemm_kernel(
    const float* __restrict__ A1, const float* __restrict__ A2,
    const float* __restrict__ W,  const float* __restrict__ bias,
    const float* __restrict__ aux, float* __restrict__ C,
    int N, int K)
{
    __shared__ float As[8][128];
    __shared__ float Bs[8][128];
    int tid = threadIdx.x;
    int bn0 = blockIdx.x * 128;
    int bm0 = blockIdx.y * 128;
    // in_proj: q,k columns come from roped input, v columns from xn
    const float* A = (EPI == EPI_QKV && bn0 >= 2 * D_) ? A2 : A1;

    int arow = tid >> 1;          // 0..127
    int acol = (tid & 1) * 4;     // 0 or 4
    const float* Ap = A + (size_t)(bm0 + arow) * K + acol;
    const float* Wp = W + (size_t)(bn0 + arow) * K + acol;

    int tx = tid & 15, ty = tid >> 4;
    float acc[8][8];
    #pragma unroll
    for (int i = 0; i < 8; i++)
        #pragma unroll
        for (int j = 0; j < 8; j++) acc[i][j] = 0.f;

    for (int k0 = 0; k0 < K; k0 += 8) {
        float4 av = *(const float4*)(Ap + k0);
        float4 wv = *(const float4*)(Wp + k0);
        __syncthreads();
        As[acol+0][arow] = av.x; As[acol+1][arow] = av.y;
        As[acol+2][arow] = av.z; As[acol+3][arow] = av.w;
        Bs[acol+0][arow] = wv.x; Bs[acol+1][arow] = wv.y;
        Bs[acol+2][arow] = wv.z; Bs[acol+3][arow] = wv.w;
        __syncthreads();
        #pragma unroll
        for (int kk = 0; kk < 8; kk++) {
            float4 a0 = *(const float4*)&As[kk][ty * 8];
            float4 a1 = *(const float4*)&As[kk][ty * 8 + 4];
            float4 b0 = *(const float4*)&Bs[kk][tx * 8];
            float4 b1 = *(const float4*)&Bs[kk][tx * 8 + 4];
            float a[8] = {a0.x,a0.y,a0.z,a0.w,a1.x,a1.y,a1.z,a1.w};
            float b[8] = {b0.x,b0.y,b0.z,b0.w,b1.x,b1.y,b1.z,b1.w};
            #pragma unroll
            for (int i = 0; i < 8; i++)
                #pragma unroll
                for (int j = 0; j < 8; j++)
                    acc[i][j] = fmaf(a[i], b[j], acc[i][j]);
        }
    }

    #pragma unroll
    for (int i = 0; i < 8; i++) {
        int m = bm0 + ty * 8 + i;
        #pragma unroll
        for (int j = 0; j < 8; j++) {
            int n = bn0 + tx * 8 + j;
            float val = acc[i][j] + bias[n];
            if (EPI == EPI_QKV) {
                int which = n >> 10;
                int h = (n >> 6) & 15;
                int d = n & 63;
                int b = m >> 11;
                int t = m & 2047;
                C[(size_t)which * (MTOK * D_) +
                  ((size_t)(b * H_ + h) * T_ + t) * HD_ + d] = val;
            } else if (EPI == EPI_Y) {
                C[(size_t)m * N + n] = val;
            } else if (EPI == EPI_SILU) {
                C[(size_t)m * N + n] = val / (1.f + expf(-val));
            } else { // EPI_OUT: out = y + ffn
                C[(size_t)m * N + n] = aux[(size_t)m * N + n] + val;
            }
        }
    }
}

// ---------------- causal flash attention, 64x64 tiles -----------------------
// grid: (T/64, B*H), 256 threads. smem: Qs[64][65], KPs[64][65] (K then P), Vs[64][65]
__global__ void __launch_bounds__(256) attn_kernel(
    const float* __restrict__ qkv, float* __restrict__ ctx)
{
    extern __shared__ float sm[];
    float* Qs  = sm;
    float* KPs = sm + 64 * 65;
    float* Vs  = sm + 2 * 64 * 65;

    int qt  = blockIdx.x;
    int bh  = blockIdx.y;
    int tid = threadIdx.x;
    int tx  = tid & 15, ty = tid >> 4;

    const float* Qb = qkv + (size_t)bh * (T_ * HD_);
    const float* Kb = qkv + (size_t)(MTOK * D_)     + (size_t)bh * (T_ * HD_);
    const float* Vb = qkv + (size_t)2 * (MTOK * D_) + (size_t)bh * (T_ * HD_);

    { // load Q tile
        int r  = tid >> 2;
        int c0 = (tid & 3) * 16;
        #pragma unroll
        for (int u = 0; u < 4; u++) {
            int c = c0 + u * 4;
            float4 v = *(const float4*)(Qb + (size_t)(qt * 64 + r) * 64 + c);
            Qs[r*65+c] = v.x; Qs[r*65+c+1] = v.y; Qs[r*65+c+2] = v.z; Qs[r*65+c+3] = v.w;
        }
    }

    float m_i[4], l_i[4], acc[4][4];
    #pragma unroll
    for (int i = 0; i < 4; i++) {
        m_i[i] = -INFINITY; l_i[i] = 0.f;
        #pragma unroll
        for (int j = 0; j < 4; j++) acc[i][j] = 0.f;
    }

    for (int kt = 0; kt <= qt; kt++) {
        __syncthreads();   // prior-iter KPs/Vs reads done; also publishes Qs on iter 0
        {                  // load K,V tiles
            int r  = tid >> 2;
            int c0 = (tid & 3) * 16;
            #pragma unroll
            for (int u = 0; u < 4; u++) {
                int c = c0 + u * 4;
                float4 kv = *(const float4*)(Kb + (size_t)(kt * 64 + r) * 64 + c);
                KPs[r*65+c] = kv.x; KPs[r*65+c+1] = kv.y; KPs[r*65+c+2] = kv.z; KPs[r*65+c+3] = kv.w;
                float4 vv = *(const float4*)(Vb + (size_t)(kt * 64 + r) * 64 + c);
                Vs[r*65+c] = vv.x; Vs[r*65+c+1] = vv.y; Vs[r*65+c+2] = vv.z; Vs[r*65+c+3] = vv.w;
            }
        }
        __syncthreads();

        // S = Q K^T  (4x4 microtile per thread)
        float s[4][4];
        #pragma unroll
        for (int i = 0; i < 4; i++)
            #pragma unroll
            for (int j = 0; j < 4; j++) s[i][j] = 0.f;
        for (int d = 0; d < 64; d++) {
            float a[4], b[4];
            #pragma unroll
            for (int i = 0; i < 4; i++) a[i] = Qs[(ty*4+i)*65 + d];
            #pragma unroll
            for (int j = 0; j < 4; j++) b[j] = KPs[(tx*4+j)*65 + d];
            #pragma unroll
            for (int i = 0; i < 4; i++)
                #pragma unroll
                for (int j = 0; j < 4; j++) s[i][j] = fmaf(a[i], b[j], s[i][j]);
        }
        __syncthreads();   // done reading K from KPs

        // scale + causal mask (only diagonal tile needs masking)
        bool diag = (kt == qt);
        #pragma unroll
        for (int i = 0; i < 4; i++) {
            int qrow = qt * 64 + ty * 4 + i;
            #pragma unroll
            for (int j = 0; j < 4; j++) {
                int kcol = kt * 64 + tx * 4 + j;
                s[i][j] *= 0.125f;               // 1/sqrt(64)
                if (diag && kcol > qrow) s[i][j] = -1e30f;
            }
        }

        // online softmax update; stage P in KPs
        #pragma unroll
        for (int i = 0; i < 4; i++) {
            float mm = fmaxf(fmaxf(s[i][0], s[i][1]), fmaxf(s[i][2], s[i][3]));
            #pragma unroll
            for (int o = 8; o; o >>= 1) mm = fmaxf(mm, __shfl_xor_sync(0xffffffffu, mm, o));
            float mn = fmaxf(m_i[i], mm);
            float alpha = expf(m_i[i] - mn);
            m_i[i] = mn;
            float rs = 0.f;
            #pragma unroll
            for (int j = 0; j < 4; j++) {
                float p = expf(s[i][j] - mn);
                KPs[(ty*4+i)*65 + tx*4 + j] = p;
                rs += p;
            }
            #pragma unroll
            for (int o = 8; o; o >>= 1) rs += __shfl_xor_sync(0xffffffffu, rs, o);
            l_i[i] = l_i[i] * alpha + rs;
            #pragma unroll
            for (int j = 0; j < 4; j++) acc[i][j] *= alpha;
        }
        __syncthreads();   // P published

        // acc += P V
        for (int jj = 0; jj < 64; jj++) {
            float a[4], b[4];
            #pragma unroll
            for (int i = 0; i < 4; i++) a[i] = KPs[(ty*4+i)*65 + jj];
            #pragma unroll
            for (int j = 0; j < 4; j++) b[j] = Vs[jj*65 + tx*4 + j];
            #pragma unroll
            for (int i = 0; i < 4; i++)
                #pragma unroll
                for (int j = 0; j < 4; j++) acc[i][j] = fmaf(a[i], b[j], acc[i][j]);
        }
    }

    // write ctx in [B,T,D] layout (so out_proj is a plain GEMM)
    int b = bh >> 4, h = bh & 15;
    #pragma unroll
    for (int i = 0; i < 4; i++) {
        int row = qt * 64 + ty * 4 + i;
        float inv = 1.f / l_i[i];
        float4 o;
        o.x = acc[i][0]*inv; o.y = acc[i][1]*inv; o.z = acc[i][2]*inv; o.w = acc[i][3]*inv;
        *(float4*)(ctx + ((size_t)(b * T_ + row) * D_) + h * HD_ + tx * 4) = o;
    }
}

// ---------------- launch ----------------------------------------------------
extern "C" void kernel_launch(void* const* d_in, const int* in_sizes, int n_in,
                              void* d_out, int out_size)
{
    const float* x     = (const float*)d_in[0];
    const float* scale = (const float*)d_in[1];
    const float* wqkv  = (const float*)d_in[2];
    const float* bqkv  = (const float*)d_in[3];
    const float* wo    = (const float*)d_in[4];
    const float* bo    = (const float*)d_in[5];
    const float* w1    = (const float*)d_in[6];
    const float* b1    = (const float*)d_in[7];
    const float* w2    = (const float*)d_in[8];
    const float* b2    = (const float*)d_in[9];
    float* out = (float*)d_out;

    float *xn, *qkr, *qkv, *ctx, *y, *yn, *h1;
    cudaGetSymbolAddress((void**)&xn,  g_xn);
    cudaGetSymbolAddress((void**)&qkr, g_qkr);
    cudaGetSymbolAddress((void**)&qkv, g_qkv);
    cudaGetSymbolAddress((void**)&ctx, g_ctx);
    cudaGetSymbolAddress((void**)&y,   g_y);
    cudaGetSymbolAddress((void**)&yn,  g_yn);
    cudaGetSymbolAddress((void**)&h1,  g_h1);

    const int ATTN_SMEM = 3 * 64 * 65 * 4;  // 49920 B > 48K default -> opt in
    cudaFuncSetAttribute(attn_kernel, cudaFuncAttributeMaxDynamicSharedMemorySize, ATTN_SMEM);

    // 1) rmsnorm + rope
    rmsnorm_kernel<true><<<MTOK, 256>>>(x, scale, xn, qkr);
    // 2) qkv projection (q,k from roped input; v from xn), scatter to [B,H,T,hd]
    gemm_kernel<EPI_QKV><<<dim3(3 * D_ / 128, MTOK / 128), 256>>>(
        qkr, xn, wqkv, bqkv, nullptr, qkv, 3 * D_, D_);
    // 3) causal attention -> ctx [B,T,D]
    attn_kernel<<<dim3(T_ / 64, B_ * H_), 256, ATTN_SMEM>>>(qkv, ctx);
    // 4) out projection -> y
    gemm_kernel<EPI_Y><<<dim3(D_ / 128, MTOK / 128), 256>>>(
        ctx, nullptr, wo, bo, nullptr, y, D_, D_);
    // 5) rmsnorm(y) -> yn
    rmsnorm_kernel<false><<<MTOK, 256>>>(y, scale, yn, nullptr);
    // 6) ffn up + silu -> h1
    gemm_kernel<EPI_SILU><<<dim3(4 * D_ / 128, MTOK / 128), 256>>>(
        yn, nullptr, w1, b1, nullptr, h1, 4 * D_, D_);
    // 7) ffn down + residual(y) -> out
    gemm_kernel<EPI_OUT><<<dim3(D_ / 128, MTOK / 128), 256>>>(
        h1, nullptr, w2, b2, y, out, D_, 4 * D_);
}